// round 13
// baseline (speedup 1.0000x reference)
#include <cuda_runtime.h>
#include <cuda_fp16.h>
#include <math_constants.h>
#include <cstdint>

#define TOKENS  32768
#define DIM     2048
#define NE      64
#define TOPK    6
#define MT      128                 // tokens per CTA
#define KCH     64                  // K per chunk
#define NCH     (DIM / KCH)         // 32
#define NTH     256
#define WSCALE_INV 0.03125f         // w pre-scaled by 32 in split kernel

// smem map (dynamic): x 2x32KB (2 x 16KB SW128 halves) | w 2x16KB | bias
#define OFFX    0
#define XBUF    32768
#define OFFW    65536
#define WBUF    16384
#define OFFB    98304
#define SMEMSZ  98560

// pre-split (fp16, w*32), pre-swizzled weights: [term][32-chunk][64 experts x 64B]
#define NC32    (DIM / 32)
__device__ __align__(16) unsigned char g_wsw[2][NC32][NE * 32 * 2];

__device__ __forceinline__ unsigned su32(const void* p) {
    return (unsigned)__cvta_generic_to_shared(p);
}
__device__ __forceinline__ void cp16(unsigned d, const void* s) {
    asm volatile("cp.async.cg.shared.global [%0], [%1], 16;" :: "r"(d), "l"(s));
}
// 64B-row XOR swizzle (validated on w tiles): bits[5:4] ^= bits[8:7]
__device__ __forceinline__ unsigned sw64(unsigned off) {
    return off ^ (((off >> 7) & 3u) << 4);
}
// 128B-row swizzle (validated on x tiles): bits[6:4] ^= bits[9:7]
__device__ __forceinline__ unsigned sw128(unsigned off) {
    return off ^ ((off >> 3) & 0x70u);
}
// 2-term fp16 split of (f0,f1): p1 = rn(f), p2 = rn(f - p1)
__device__ __forceinline__ void split2h(float f0, float f1, unsigned& p1, unsigned& p2) {
    __half2 h1 = __floats2half2_rn(f0, f1);
    p1 = *(unsigned*)&h1;
    float2 g = __half22float2(h1);
    __half2 h2 = __floats2half2_rn(f0 - g.x, f1 - g.y);
    p2 = *(unsigned*)&h2;
}
__device__ __forceinline__ void ldsm4(unsigned b[4], unsigned addr) {
    asm volatile("ldmatrix.sync.aligned.m8n8.x4.shared.b16 {%0,%1,%2,%3}, [%4];"
                 : "=r"(b[0]), "=r"(b[1]), "=r"(b[2]), "=r"(b[3]) : "r"(addr));
}
// accumulate: C += A*B (fp16 in, fp32 acc)
__device__ __forceinline__ void mma16816(float* c, const unsigned* a,
                                         unsigned b0, unsigned b1) {
    asm volatile(
        "mma.sync.aligned.m16n8k16.row.col.f32.f16.f16.f32 "
        "{%0,%1,%2,%3}, {%4,%5,%6,%7}, {%8,%9}, {%0,%1,%2,%3};"
        : "+f"(c[0]), "+f"(c[1]), "+f"(c[2]), "+f"(c[3])
        : "r"(a[0]), "r"(a[1]), "r"(a[2]), "r"(a[3]), "r"(b0), "r"(b1));
}
// zero-start: C = A*B
__device__ __forceinline__ void mma16816_z(float* c, const unsigned* a,
                                           unsigned b0, unsigned b1) {
    asm volatile(
        "mma.sync.aligned.m16n8k16.row.col.f32.f16.f16.f32 "
        "{%0,%1,%2,%3}, {%4,%5,%6,%7}, {%8,%9}, {%10,%11,%12,%13};"
        : "=f"(c[0]), "=f"(c[1]), "=f"(c[2]), "=f"(c[3])
        : "r"(a[0]), "r"(a[1]), "r"(a[2]), "r"(a[3]), "r"(b0), "r"(b1),
          "f"(0.0f), "f"(0.0f), "f"(0.0f), "f"(0.0f));
}

// ---- pre-kernel: 2-term fp16 split of 32*w, ldmatrix-swizzled rows of 64B ----
__global__ void split_w_kernel(const float* __restrict__ w) {
    int idx = blockIdx.x * 256 + threadIdx.x;     // e*DIM + k, < 131072
    int e = idx >> 11, k = idx & (DIM - 1);
    float v = w[idx] * 32.0f;                     // exact scale, undone in epilogue
    __half h1 = __float2half_rn(v);
    float f1 = __half2float(h1);
    __half h2 = __float2half_rn(v - f1);
    int c = k >> 5, kk = k & 31;
    unsigned off = ((unsigned)e << 6) | ((unsigned)kk << 1);
    unsigned sw = sw64(off);
    *(unsigned short*)&g_wsw[0][c][sw] = *(unsigned short*)&h1;
    *(unsigned short*)&g_wsw[1][c][sw] = *(unsigned short*)&h2;
}

__global__ __launch_bounds__(NTH, 2)
void gate_hmma_kernel(const float* __restrict__ x,
                      const float* __restrict__ bias,
                      float* __restrict__ out) {
    extern __shared__ unsigned char sm[];

    const int tid = threadIdx.x;
    const int wid = tid >> 5;
    const int L   = tid & 31;
    const int r4  = L >> 2;          // 0..7
    const int cq  = L & 3;           // 0..3
    const int mg  = wid & 3;         // M-group: rows [mg*32, mg*32+32)
    const int ng  = wid >> 2;        // N-group: experts [ng*32, ng*32+32)
    const int t0  = blockIdx.x * MT;

    if (tid < NE) ((float*)(sm + OFFB))[tid] = bias[tid];

    // ---- x cp.async: thread covers q=(tid&7), rows (tid>>3)+{0,32,64,96}, kb 0..1 ----
    const float* xp = x + (size_t)(t0 + (tid >> 3)) * DIM + (tid & 7) * 4;
    unsigned offx0 = (unsigned)((tid >> 3) << 7) | (unsigned)((tid & 7) << 4);
    const unsigned xdst0 = su32(sm + OFFX) + sw128(offx0);

    // ---- w cp.async: block i (0..3): kb = i>>1, term = i&1; one 16B unit/thread ----
    const unsigned char* wp[4];
#pragma unroll
    for (int i = 0; i < 4; i++)
        wp[i] = &g_wsw[i & 1][i >> 1][tid << 4];
    const unsigned wdst0 = su32(sm + OFFW) + (tid << 4);

    // fp32 running logits; one drain per chunk (chain depth 12, validated)
    float run[2][4][4];
#pragma unroll
    for (int f = 0; f < 2; f++)
#pragma unroll
        for (int n = 0; n < 4; n++)
#pragma unroll
            for (int i = 0; i < 4; i++) run[f][n][i] = 0.0f;

    // ---- prologue: chunk 0 -> slot 0 ----
#pragma unroll
    for (int i = 0; i < 8; i++)
        cp16(xdst0 + (i >> 2) * 16384 + (i & 3) * 4096, xp + (i & 3) * 32 * DIM + (i >> 2) * 32);
    xp += KCH;
#pragma unroll
    for (int i = 0; i < 4; i++)
        cp16(wdst0 + (i >> 1) * 8192 + (i & 1) * 4096, wp[i]);
    asm volatile("cp.async.commit_group;");

    const int m  = L >> 3;
    const int rr = L & 7;

    for (int ch = 0; ch < NCH; ch++) {
        asm volatile("cp.async.wait_group 0;");
        __syncthreads();   // chunk ch visible everywhere; slot ch-1 reads all done

        // prefetch chunk ch+1 into the other slot (full compute window to land)
        if (ch + 1 < NCH) {
            unsigned sl = (unsigned)((ch + 1) & 1);
#pragma unroll
            for (int i = 0; i < 8; i++)
                cp16(xdst0 + sl * XBUF + (i >> 2) * 16384 + (i & 3) * 4096,
                     xp + (i & 3) * 32 * DIM + (i >> 2) * 32);
            xp += KCH;
#pragma unroll
            for (int i = 0; i < 4; i++) {
                cp16(wdst0 + sl * WBUF + (i >> 1) * 8192 + (i & 1) * 4096,
                     wp[i] + (size_t)(ch + 1) * 8192);
            }
            asm volatile("cp.async.commit_group;");
        }

        const unsigned xb = su32(sm + OFFX) + (ch & 1) * XBUF;
        const unsigned wb = su32(sm + OFFW) + (ch & 1) * WBUF;

        float cc[2][4][4];                   // chunk-local tensor-core chains
#pragma unroll
        for (int s = 0; s < 4; s++) {        // four k16 steps per chunk
            const unsigned xkb = xb + (s >> 1) * 16384;
            const unsigned wkb = wb + (s >> 1) * 8192;
            const int sp = s & 1;

            // ---- A fragments: 2 m16 frags (rows mg*32 + f*16 + ...) ----
            unsigned a1[2][4], a2[2][4];
#pragma unroll
            for (int f = 0; f < 2; f++) {
                const int R0f = mg * 32 + f * 16 + r4;
#pragma unroll
                for (int half = 0; half < 2; half++) {
#pragma unroll
                    for (int rowi = 0; rowi < 2; rowi++) {
                        int row = R0f + rowi * 8;
                        unsigned off = ((unsigned)row << 7)
                                     + ((unsigned)(sp * 16 + cq * 2 + half * 8) << 2);
                        float f0, f1;
                        asm volatile("ld.shared.v2.f32 {%0,%1}, [%2];"
                                     : "=f"(f0), "=f"(f1) : "r"(xkb + sw128(off)));
                        int pi = half * 2 + rowi;
                        split2h(f0, f1, a1[f][pi], a2[f][pi]);
                    }
                }
            }
            // ---- B terms (N32: 2 n16 groups) + HMMA: 3 products per C ----
#pragma unroll
            for (int p = 0; p < 2; p++) {
                int e = ng * 32 + p * 16 + (m >> 1) * 8 + rr;
                unsigned off = ((unsigned)e << 6) + sp * 32 + (m & 1) * 16;
                unsigned swo = sw64(off);
                unsigned b1[4], b2[4];
                ldsm4(b1, wkb + swo);            // w term 1
                ldsm4(b2, wkb + 4096 + swo);     // w term 2
#pragma unroll
                for (int f = 0; f < 2; f++) {
                    float* c0 = cc[f][2 * p + 0];
                    float* c1 = cc[f][2 * p + 1];
                    if (s == 0) {
                        mma16816_z(c0, a1[f], b1[0], b1[1]);
                        mma16816_z(c1, a1[f], b1[2], b1[3]);
                    } else {
                        mma16816(c0, a1[f], b1[0], b1[1]);
                        mma16816(c1, a1[f], b1[2], b1[3]);
                    }
                    mma16816(c0, a2[f], b1[0], b1[1]);
                    mma16816(c1, a2[f], b1[2], b1[3]);
                    mma16816(c0, a1[f], b2[0], b2[1]);
                    mma16816(c1, a1[f], b2[2], b2[3]);
                }
            }
        }
        // ---- drain once per chunk: IEEE fp32 adds ----
#pragma unroll
        for (int f = 0; f < 2; f++)
#pragma unroll
            for (int nt = 0; nt < 4; nt++)
#pragma unroll
                for (int i = 0; i < 4; i++) run[f][nt][i] += cc[f][nt][i];
    }

    __syncthreads();   // all warps done with mainloop buffers before overlay

    // ---- scatter logits to smem [128][65] (overlays mainloop buffers) ----
    float* lg = (float*)sm;
#pragma unroll
    for (int f = 0; f < 2; f++)
#pragma unroll
        for (int nt = 0; nt < 4; nt++)
#pragma unroll
            for (int i = 0; i < 4; i++) {
                int tk = mg * 32 + f * 16 + r4 + ((i >= 2) ? 8 : 0);
                int ex = ng * 32 + nt * 8 + cq * 2 + (i & 1);
                lg[tk * 65 + ex] = run[f][nt][i];
            }
    __syncthreads();

    if (tid < MT) {
        float sc[NE];
#pragma unroll
        for (int e = 0; e < NE; e++) sc[e] = lg[tid * 65 + e] * WSCALE_INV;  // undo w*32

        float mx = -CUDART_INF_F;
#pragma unroll
        for (int e = 0; e < NE; e++) mx = fmaxf(mx, sc[e]);
        float sum = 0.0f;
#pragma unroll
        for (int e = 0; e < NE; e++) { sc[e] = __expf(sc[e] - mx); sum += sc[e]; }
        float inv = 1.0f / sum;
#pragma unroll
        for (int e = 0; e < NE; e++) sc[e] *= inv;

        const float* bs = (const float*)(sm + OFFB);
        unsigned long long taken = 0ull;
        const int t = t0 + tid;
        float* wout = out + (size_t)t * TOPK;
        float* iout = out + (size_t)TOKENS * TOPK + (size_t)t * TOPK;

#pragma unroll
        for (int sidx = 0; sidx < TOPK; sidx++) {
            float best = -CUDART_INF_F;
            float bsc = 0.0f;
            int be = 0;
#pragma unroll
            for (int e = 0; e < NE; e++) {
                float v = sc[e] + bs[e];
                bool ok = ((taken >> e) & 1ull) == 0ull;
                if (ok && v > best) { best = v; bsc = sc[e]; be = e; }
            }
            taken |= (1ull << be);
            wout[sidx] = bsc;        // ROUTE_SCALE == 1.0
            iout[sidx] = (float)be;
        }
    }
}

extern "C" void kernel_launch(void* const* d_in, const int* in_sizes, int n_in,
                              void* d_out, int out_size) {
    const float* x    = (const float*)d_in[0];
    const float* w    = (const float*)d_in[1];
    const float* bias = (const float*)d_in[2];
    float* out        = (float*)d_out;

    cudaFuncSetAttribute(gate_hmma_kernel,
                         cudaFuncAttributeMaxDynamicSharedMemorySize, SMEMSZ);

    split_w_kernel<<<(NE * DIM) / 256, 256>>>(w);
    gate_hmma_kernel<<<TOKENS / MT, NTH, SMEMSZ>>>(x, bias, out);
}

// round 15
// speedup vs baseline: 1.0463x; 1.0463x over previous
#include <cuda_runtime.h>
#include <cuda_fp16.h>
#include <math_constants.h>
#include <cstdint>

#define TOKENS  32768
#define DIM     2048
#define NE      64
#define TOPK    6
#define MT      128                 // tokens per CTA
#define KCH     64                  // K per chunk
#define NCH     (DIM / KCH)         // 32
#define NTH     256
#define WSCALE_INV 0.03125f         // w pre-scaled by 32 in split kernel

// smem map (dynamic): x 2x32KB (2 x 16KB SW128 halves) | w 2x16KB | bias
#define OFFX    0
#define XBUF    32768
#define OFFW    65536
#define WBUF    16384
#define OFFB    98304
#define SMEMSZ  98560

// pre-split (fp16, w*32), pre-swizzled weights: [term][32-chunk][64 experts x 64B]
#define NC32    (DIM / 32)
__device__ __align__(16) unsigned char g_wsw[2][NC32][NE * 32 * 2];

__device__ __forceinline__ unsigned su32(const void* p) {
    return (unsigned)__cvta_generic_to_shared(p);
}
__device__ __forceinline__ void cp16(unsigned d, const void* s) {
    asm volatile("cp.async.cg.shared.global [%0], [%1], 16;" :: "r"(d), "l"(s));
}
// 64B-row XOR swizzle (validated on w tiles): bits[5:4] ^= bits[8:7]
__device__ __forceinline__ unsigned sw64(unsigned off) {
    return off ^ (((off >> 7) & 3u) << 4);
}
// 128B-row swizzle (validated on x tiles): bits[6:4] ^= bits[9:7]
__device__ __forceinline__ unsigned sw128(unsigned off) {
    return off ^ ((off >> 3) & 0x70u);
}
// 2-term fp16 split of (f0,f1): p1 = rn(f), p2 = rn(f - p1)
__device__ __forceinline__ void split2h(float f0, float f1, unsigned& p1, unsigned& p2) {
    __half2 h1 = __floats2half2_rn(f0, f1);
    p1 = *(unsigned*)&h1;
    float2 g = __half22float2(h1);
    __half2 h2 = __floats2half2_rn(f0 - g.x, f1 - g.y);
    p2 = *(unsigned*)&h2;
}
__device__ __forceinline__ void ldsm4(unsigned b[4], unsigned addr) {
    asm volatile("ldmatrix.sync.aligned.m8n8.x4.shared.b16 {%0,%1,%2,%3}, [%4];"
                 : "=r"(b[0]), "=r"(b[1]), "=r"(b[2]), "=r"(b[3]) : "r"(addr));
}
// accumulate: C += A*B (fp16 in, fp32 acc)
__device__ __forceinline__ void mma16816(float* c, const unsigned* a,
                                         unsigned b0, unsigned b1) {
    asm volatile(
        "mma.sync.aligned.m16n8k16.row.col.f32.f16.f16.f32 "
        "{%0,%1,%2,%3}, {%4,%5,%6,%7}, {%8,%9}, {%0,%1,%2,%3};"
        : "+f"(c[0]), "+f"(c[1]), "+f"(c[2]), "+f"(c[3])
        : "r"(a[0]), "r"(a[1]), "r"(a[2]), "r"(a[3]), "r"(b0), "r"(b1));
}
// zero-start: C = A*B
__device__ __forceinline__ void mma16816_z(float* c, const unsigned* a,
                                           unsigned b0, unsigned b1) {
    asm volatile(
        "mma.sync.aligned.m16n8k16.row.col.f32.f16.f16.f32 "
        "{%0,%1,%2,%3}, {%4,%5,%6,%7}, {%8,%9}, {%10,%11,%12,%13};"
        : "=f"(c[0]), "=f"(c[1]), "=f"(c[2]), "=f"(c[3])
        : "r"(a[0]), "r"(a[1]), "r"(a[2]), "r"(a[3]), "r"(b0), "r"(b1),
          "f"(0.0f), "f"(0.0f), "f"(0.0f), "f"(0.0f));
}

// ---- pre-kernel: 2-term fp16 split of 32*w, ldmatrix-swizzled rows of 64B ----
__global__ void split_w_kernel(const float* __restrict__ w) {
    int idx = blockIdx.x * 256 + threadIdx.x;     // e*DIM + k, < 131072
    int e = idx >> 11, k = idx & (DIM - 1);
    float v = w[idx] * 32.0f;                     // exact scale, undone in epilogue
    __half h1 = __float2half_rn(v);
    float f1 = __half2float(h1);
    __half h2 = __float2half_rn(v - f1);
    int c = k >> 5, kk = k & 31;
    unsigned off = ((unsigned)e << 6) | ((unsigned)kk << 1);
    unsigned sw = sw64(off);
    *(unsigned short*)&g_wsw[0][c][sw] = *(unsigned short*)&h1;
    *(unsigned short*)&g_wsw[1][c][sw] = *(unsigned short*)&h2;
}

__global__ __launch_bounds__(NTH, 2)
void gate_hmma_kernel(const float* __restrict__ x,
                      const float* __restrict__ bias,
                      float* __restrict__ out) {
    extern __shared__ unsigned char sm[];

    const int tid = threadIdx.x;
    const int wid = tid >> 5;
    const int L   = tid & 31;
    const int r4  = L >> 2;          // 0..7
    const int cq  = L & 3;           // 0..3
    const int t0  = blockIdx.x * MT;

    if (tid < NE) ((float*)(sm + OFFB))[tid] = bias[tid];

    // ---- x cp.async: thread covers q=(tid&7), rows (tid>>3)+{0,32,64,96}, kb 0..1 ----
    const float* xp = x + (size_t)(t0 + (tid >> 3)) * DIM + (tid & 7) * 4;
    unsigned offx0 = (unsigned)((tid >> 3) << 7) | (unsigned)((tid & 7) << 4);
    const unsigned xdst0 = su32(sm + OFFX) + sw128(offx0);

    // ---- w cp.async: block i (0..3): kb = i>>1, term = i&1; one 16B unit/thread ----
    const unsigned char* wp[4];
#pragma unroll
    for (int i = 0; i < 4; i++)
        wp[i] = &g_wsw[i & 1][i >> 1][tid << 4];
    const unsigned wdst0 = su32(sm + OFFW) + (tid << 4);

    // fp32 running logits; one drain per chunk (chain depth 12, validated)
    float run[8][4];
#pragma unroll
    for (int n = 0; n < 8; n++)
#pragma unroll
        for (int i = 0; i < 4; i++) run[n][i] = 0.0f;

    // ---- prologue: chunk 0 -> slot 0 ----
#pragma unroll
    for (int i = 0; i < 8; i++)
        cp16(xdst0 + (i >> 2) * 16384 + (i & 3) * 4096, xp + (i & 3) * 32 * DIM + (i >> 2) * 32);
    xp += KCH;
#pragma unroll
    for (int i = 0; i < 4; i++)
        cp16(wdst0 + (i >> 1) * 8192 + (i & 1) * 4096, wp[i]);
    asm volatile("cp.async.commit_group;");

    const int R0 = wid * 16 + r4;
    const int m  = L >> 3;
    const int rr = L & 7;

    // A-load swizzled offsets for the 4 k-steps (relative to x slot base):
    // step s: sub-buffer (s>>1)*16384, cols (s&1)*16 + cq*2 + half*8
    unsigned aoff[4][4];   // [s][half*2+rowi]
#pragma unroll
    for (int s = 0; s < 4; s++)
#pragma unroll
        for (int half = 0; half < 2; half++)
#pragma unroll
            for (int rowi = 0; rowi < 2; rowi++) {
                int row = R0 + rowi * 8;
                unsigned off = ((unsigned)row << 7)
                             + ((unsigned)((s & 1) * 16 + cq * 2 + half * 8) << 2);
                aoff[s][half * 2 + rowi] = (unsigned)((s >> 1) * 16384) + sw128(off);
            }

    for (int ch = 0; ch < NCH; ch++) {
        asm volatile("cp.async.wait_group 0;");
        __syncthreads();   // chunk ch visible everywhere; slot ch-1 reads all done

        // prefetch chunk ch+1 into the other slot (full compute window to land)
        if (ch + 1 < NCH) {
            unsigned sl = (unsigned)((ch + 1) & 1);
#pragma unroll
            for (int i = 0; i < 8; i++)
                cp16(xdst0 + sl * XBUF + (i >> 2) * 16384 + (i & 3) * 4096,
                     xp + (i & 3) * 32 * DIM + (i >> 2) * 32);
            xp += KCH;
#pragma unroll
            for (int i = 0; i < 4; i++) {
                cp16(wdst0 + sl * WBUF + (i >> 1) * 8192 + (i & 1) * 4096,
                     wp[i] + (size_t)(ch + 1) * 8192);
            }
            asm volatile("cp.async.commit_group;");
        }

        const unsigned xb = su32(sm + OFFX) + (ch & 1) * XBUF;
        const unsigned wb = su32(sm + OFFW) + (ch & 1) * WBUF;

        float cc[8][4];                      // chunk-local tensor-core chains

        // ---- software-pipelined A fragments: load step 0 up front ----
        unsigned a1[2][4], a2[2][4];
#pragma unroll
        for (int pi = 0; pi < 4; pi++) {
            float f0, f1;
            asm volatile("ld.shared.v2.f32 {%0,%1}, [%2];"
                         : "=f"(f0), "=f"(f1) : "r"(xb + aoff[0][pi]));
            split2h(f0, f1, a1[0][pi], a2[0][pi]);
        }

#pragma unroll
        for (int s = 0; s < 4; s++) {        // four k16 steps per chunk
            const unsigned wkb = wb + (s >> 1) * 8192;
            const int sp = s & 1;
            const int cur = s & 1;           // a-frag buffer index for step s
            const int nxt = cur ^ 1;

#pragma unroll
            for (int p = 0; p < 4; p++) {
                int e = p * 16 + (m >> 1) * 8 + rr;
                unsigned off = ((unsigned)e << 6) + sp * 32 + (m & 1) * 16;
                unsigned swo = sw64(off);
                unsigned b1[4], b2[4];
                ldsm4(b1, wkb + swo);            // w term 1
                ldsm4(b2, wkb + 4096 + swo);     // w term 2

                // hoisted A-load of step s+1: overlaps this step's ldsm/MMA
                if (p == 0 && s < 3) {
#pragma unroll
                    for (int pi = 0; pi < 4; pi++) {
                        float f0, f1;
                        asm volatile("ld.shared.v2.f32 {%0,%1}, [%2];"
                                     : "=f"(f0), "=f"(f1) : "r"(xb + aoff[s + 1][pi]));
                        split2h(f0, f1, a1[nxt][pi], a2[nxt][pi]);
                    }
                }

                float* c0 = cc[2 * p + 0];
                float* c1 = cc[2 * p + 1];
                if (s == 0) {
                    mma16816_z(c0, a1[cur], b1[0], b1[1]);
                    mma16816_z(c1, a1[cur], b1[2], b1[3]);
                } else {
                    mma16816(c0, a1[cur], b1[0], b1[1]);
                    mma16816(c1, a1[cur], b1[2], b1[3]);
                }
                mma16816(c0, a2[cur], b1[0], b1[1]);
                mma16816(c1, a2[cur], b1[2], b1[3]);
                mma16816(c0, a1[cur], b2[0], b2[1]);
                mma16816(c1, a1[cur], b2[2], b2[3]);
            }
        }
        // ---- drain once per chunk: IEEE fp32 adds ----
#pragma unroll
        for (int nt = 0; nt < 8; nt++)
#pragma unroll
            for (int i = 0; i < 4; i++) run[nt][i] += cc[nt][i];
    }

    __syncthreads();   // all warps done with mainloop buffers before overlay

    // ---- scatter logits to smem [128][65] (overlays mainloop buffers) ----
    float* lg = (float*)sm;
#pragma unroll
    for (int nt = 0; nt < 8; nt++)
#pragma unroll
        for (int i = 0; i < 4; i++) {
            int tk = R0 + ((i >= 2) ? 8 : 0);
            int ex = nt * 8 + cq * 2 + (i & 1);
            lg[tk * 65 + ex] = run[nt][i];
        }
    __syncthreads();

    if (tid < MT) {
        float sc[NE];
#pragma unroll
        for (int e = 0; e < NE; e++) sc[e] = lg[tid * 65 + e] * WSCALE_INV;  // undo w*32

        float mx = -CUDART_INF_F;
#pragma unroll
        for (int e = 0; e < NE; e++) mx = fmaxf(mx, sc[e]);
        float sum = 0.0f;
#pragma unroll
        for (int e = 0; e < NE; e++) { sc[e] = __expf(sc[e] - mx); sum += sc[e]; }
        float inv = 1.0f / sum;
#pragma unroll
        for (int e = 0; e < NE; e++) sc[e] *= inv;

        const float* bs = (const float*)(sm + OFFB);
        unsigned long long taken = 0ull;
        const int t = t0 + tid;
        float* wout = out + (size_t)t * TOPK;
        float* iout = out + (size_t)TOKENS * TOPK + (size_t)t * TOPK;

#pragma unroll
        for (int sidx = 0; sidx < TOPK; sidx++) {
            float best = -CUDART_INF_F;
            float bsc = 0.0f;
            int be = 0;
#pragma unroll
            for (int e = 0; e < NE; e++) {
                float v = sc[e] + bs[e];
                bool ok = ((taken >> e) & 1ull) == 0ull;
                if (ok && v > best) { best = v; bsc = sc[e]; be = e; }
            }
            taken |= (1ull << be);
            wout[sidx] = bsc;        // ROUTE_SCALE == 1.0
            iout[sidx] = (float)be;
        }
    }
}

extern "C" void kernel_launch(void* const* d_in, const int* in_sizes, int n_in,
                              void* d_out, int out_size) {
    const float* x    = (const float*)d_in[0];
    const float* w    = (const float*)d_in[1];
    const float* bias = (const float*)d_in[2];
    float* out        = (float*)d_out;

    cudaFuncSetAttribute(gate_hmma_kernel,
                         cudaFuncAttributeMaxDynamicSharedMemorySize, SMEMSZ);

    split_w_kernel<<<(NE * DIM) / 256, 256>>>(w);
    gate_hmma_kernel<<<TOKENS / MT, NTH, SMEMSZ>>>(x, bias, out);
}

// round 16
// speedup vs baseline: 1.0489x; 1.0025x over previous
#include <cuda_runtime.h>
#include <cuda_fp16.h>
#include <math_constants.h>
#include <cstdint>

#define TOKENS  32768
#define DIM     2048
#define NE      64
#define TOPK    6
#define MT      128                 // tokens per CTA
#define KCH     32                  // K per chunk
#define NCH     (DIM / KCH)         // 64
#define NTH     256
#define NSLOT   4
#define WSCALE_INV 0.03125f         // w pre-scaled by 32 in split kernel

// smem map (dynamic): x 4x16KB | w 4x8KB | bias | mbarriers
#define OFFX    0
#define XBUF    16384
#define OFFW    65536
#define WBUF    8192
#define OFFB    98304
#define OFFMB   98560               // full[0..3] at +0..31, empty[0..3] at +32..63
#define SMEMSZ  98688

// pre-split (fp16, w*32), pre-swizzled weights: [term][32-chunk][64 experts x 64B]
__device__ __align__(16) unsigned char g_wsw[2][NCH][NE * KCH * 2];

__device__ __forceinline__ unsigned su32(const void* p) {
    return (unsigned)__cvta_generic_to_shared(p);
}
__device__ __forceinline__ void cp16(unsigned d, const void* s) {
    asm volatile("cp.async.cg.shared.global [%0], [%1], 16;" :: "r"(d), "l"(s));
}
// 64B-row XOR swizzle (w tiles): bits[5:4] ^= bits[8:7]
__device__ __forceinline__ unsigned sw64(unsigned off) {
    return off ^ (((off >> 7) & 3u) << 4);
}
// 128B-row swizzle (x tiles): bits[6:4] ^= bits[9:7]
__device__ __forceinline__ unsigned sw128(unsigned off) {
    return off ^ ((off >> 3) & 0x70u);
}
// 2-term fp16 split of (f0,f1): p1 = rn(f), p2 = rn(f - p1)
__device__ __forceinline__ void split2h(float f0, float f1, unsigned& p1, unsigned& p2) {
    __half2 h1 = __floats2half2_rn(f0, f1);
    p1 = *(unsigned*)&h1;
    float2 g = __half22float2(h1);
    __half2 h2 = __floats2half2_rn(f0 - g.x, f1 - g.y);
    p2 = *(unsigned*)&h2;
}
__device__ __forceinline__ void ldsm4(unsigned b[4], unsigned addr) {
    asm volatile("ldmatrix.sync.aligned.m8n8.x4.shared.b16 {%0,%1,%2,%3}, [%4];"
                 : "=r"(b[0]), "=r"(b[1]), "=r"(b[2]), "=r"(b[3]) : "r"(addr));
}
// accumulate: C += A*B (fp16 in, fp32 acc)
__device__ __forceinline__ void mma16816(float* c, const unsigned* a,
                                         unsigned b0, unsigned b1) {
    asm volatile(
        "mma.sync.aligned.m16n8k16.row.col.f32.f16.f16.f32 "
        "{%0,%1,%2,%3}, {%4,%5,%6,%7}, {%8,%9}, {%0,%1,%2,%3};"
        : "+f"(c[0]), "+f"(c[1]), "+f"(c[2]), "+f"(c[3])
        : "r"(a[0]), "r"(a[1]), "r"(a[2]), "r"(a[3]), "r"(b0), "r"(b1));
}
// zero-start: C = A*B
__device__ __forceinline__ void mma16816_z(float* c, const unsigned* a,
                                           unsigned b0, unsigned b1) {
    asm volatile(
        "mma.sync.aligned.m16n8k16.row.col.f32.f16.f16.f32 "
        "{%0,%1,%2,%3}, {%4,%5,%6,%7}, {%8,%9}, {%10,%11,%12,%13};"
        : "=f"(c[0]), "=f"(c[1]), "=f"(c[2]), "=f"(c[3])
        : "r"(a[0]), "r"(a[1]), "r"(a[2]), "r"(a[3]), "r"(b0), "r"(b1),
          "f"(0.0f), "f"(0.0f), "f"(0.0f), "f"(0.0f));
}
// spin-wait on mbarrier phase parity (acquire)
__device__ __forceinline__ void mwait(unsigned mb, unsigned ph) {
    asm volatile(
        "{\n\t.reg .pred P;\n"
        "W%=:\n\tmbarrier.try_wait.parity.acquire.cta.shared::cta.b64 P, [%0], %1, 0x989680;\n"
        "\t@P bra D%=;\n\tbra W%=;\nD%=:\n\t}"
        :: "r"(mb), "r"(ph) : "memory");
}

// ---- pre-kernel: 2-term fp16 split of 32*w, ldmatrix-swizzled rows of 64B ----
__global__ void split_w_kernel(const float* __restrict__ w) {
    int idx = blockIdx.x * 256 + threadIdx.x;     // e*DIM + k, < 131072
    int e = idx >> 11, k = idx & (DIM - 1);
    float v = w[idx] * 32.0f;                     // exact scale, undone in epilogue
    __half h1 = __float2half_rn(v);
    float f1 = __half2float(h1);
    __half h2 = __float2half_rn(v - f1);
    int c = k >> 5, kk = k & 31;
    unsigned off = ((unsigned)e << 6) | ((unsigned)kk << 1);
    unsigned sw = sw64(off);
    *(unsigned short*)&g_wsw[0][c][sw] = *(unsigned short*)&h1;
    *(unsigned short*)&g_wsw[1][c][sw] = *(unsigned short*)&h2;
}

__global__ __launch_bounds__(NTH, 2)
void gate_hmma_kernel(const float* __restrict__ x,
                      const float* __restrict__ bias,
                      float* __restrict__ out) {
    extern __shared__ unsigned char sm[];

    const int tid = threadIdx.x;
    const int wid = tid >> 5;
    const int L   = tid & 31;
    const int r4  = L >> 2;          // 0..7
    const int cq  = L & 3;           // 0..3
    const int t0  = blockIdx.x * MT;

    const unsigned mbF = su32(sm + OFFMB);        // full[i]  = mbF + 8*i
    const unsigned mbE = su32(sm + OFFMB) + 32;   // empty[i] = mbE + 8*i

    if (tid == 0) {
#pragma unroll
        for (int i = 0; i < NSLOT; i++) {
            asm volatile("mbarrier.init.shared.b64 [%0], %1;" :: "r"(mbF + 8 * i), "r"(NTH) : "memory");
            asm volatile("mbarrier.init.shared.b64 [%0], %1;" :: "r"(mbE + 8 * i), "r"(NTH) : "memory");
        }
    }
    if (tid < NE) ((float*)(sm + OFFB))[tid] = bias[tid];
    __syncthreads();   // barrier-init + bias visible

    // ---- per-thread cp.async units (R8 mapping) ----
    // x: 4 units; unit i: row = (tid>>3)+32i, q = tid&7
    const float* xsrc[4]; unsigned xdst[4];
#pragma unroll
    for (int i = 0; i < 4; i++) {
        int row = (tid >> 3) + 32 * i, q = tid & 7;
        xsrc[i] = x + (size_t)(t0 + row) * DIM + q * 4;
        xdst[i] = su32(sm + OFFX) + sw128(((unsigned)row << 7) | ((unsigned)q << 4));
    }
    // w: 2 units; unit i = term i, 16B offset (tid&255)<<4  (tid<256 so just tid<<4)
    unsigned wdst[2];
#pragma unroll
    for (int i = 0; i < 2; i++)
        wdst[i] = su32(sm + OFFW) + i * 4096 + ((tid & 255) << 4);

    // fp32 running logits; drain per chunk (chain 6 — R8-validated)
    float run[8][4];
#pragma unroll
    for (int n = 0; n < 8; n++)
#pragma unroll
        for (int i = 0; i < 4; i++) run[n][i] = 0.0f;

    // ---- prologue: chunks 0,1 -> slots 0,1 ----
#pragma unroll
    for (int c = 0; c < 2; c++) {
#pragma unroll
        for (int i = 0; i < 4; i++) cp16(xdst[i] + c * XBUF, xsrc[i] + c * KCH);
#pragma unroll
        for (int i = 0; i < 2; i++) cp16(wdst[i] + c * WBUF, &g_wsw[i][c][(tid & 255) << 4]);
        asm volatile("cp.async.mbarrier.arrive.noinc.shared.b64 [%0];" :: "r"(mbF + 8 * c) : "memory");
    }

    const int R0 = wid * 16 + r4;
    const int m  = L >> 3;
    const int rr = L & 7;

    for (int ch = 0; ch < NCH; ch++) {
        const unsigned sl = (unsigned)(ch & 3);
        mwait(mbF + 8 * sl, (unsigned)((ch >> 2) & 1));   // chunk ch data landed

        // ---- prefetch chunk ch+2 into slot (ch+2)&3 ----
        const int c2 = ch + 2;
        if (c2 < NCH) {
            const unsigned s2 = (unsigned)(c2 & 3);
            if (c2 >= NSLOT)                                // slot last read at c2-4
                mwait(mbE + 8 * s2, (unsigned)(((c2 - NSLOT) >> 2) & 1));
#pragma unroll
            for (int i = 0; i < 4; i++) cp16(xdst[i] + s2 * XBUF, xsrc[i] + (size_t)c2 * KCH);
#pragma unroll
            for (int i = 0; i < 2; i++) cp16(wdst[i] + s2 * WBUF, &g_wsw[i][c2][(tid & 255) << 4]);
            asm volatile("cp.async.mbarrier.arrive.noinc.shared.b64 [%0];" :: "r"(mbF + 8 * s2) : "memory");
        }

        const unsigned xb = su32(sm + OFFX) + sl * XBUF;
        const unsigned wb = su32(sm + OFFW) + sl * WBUF;

        float cc[8][4];                      // chunk-local tensor-core chains
#pragma unroll
        for (int s = 0; s < 2; s++) {        // two k16 steps per chunk
            // ---- A fragments: LDS pairs + 2-term fp16 split ----
            unsigned a1[4], a2[4];
#pragma unroll
            for (int half = 0; half < 2; half++) {
#pragma unroll
                for (int rowi = 0; rowi < 2; rowi++) {
                    int row = R0 + rowi * 8;
                    unsigned off = ((unsigned)row << 7)
                                 + ((unsigned)(s * 16 + cq * 2 + half * 8) << 2);
                    float f0, f1;
                    asm volatile("ld.shared.v2.f32 {%0,%1}, [%2];"
                                 : "=f"(f0), "=f"(f1) : "r"(xb + sw128(off)));
                    int pi = half * 2 + rowi;
                    split2h(f0, f1, a1[pi], a2[pi]);
                }
            }
            // ---- B terms + HMMA: 3 products per C per k-step ----
#pragma unroll
            for (int p = 0; p < 4; p++) {
                int e = p * 16 + (m >> 1) * 8 + rr;
                unsigned off = ((unsigned)e << 6) + s * 32 + (m & 1) * 16;
                unsigned swo = sw64(off);
                unsigned b1[4], b2[4];
                ldsm4(b1, wb + swo);            // w term 1
                ldsm4(b2, wb + 4096 + swo);     // w term 2
                float* c0 = cc[2 * p + 0];
                float* c1 = cc[2 * p + 1];
                if (s == 0) {
                    mma16816_z(c0, a1, b1[0], b1[1]);
                    mma16816_z(c1, a1, b1[2], b1[3]);
                } else {
                    mma16816(c0, a1, b1[0], b1[1]);
                    mma16816(c1, a1, b1[2], b1[3]);
                }
                mma16816(c0, a2, b1[0], b1[1]);
                mma16816(c1, a2, b1[2], b1[3]);
                mma16816(c0, a1, b2[0], b2[1]);
                mma16816(c1, a1, b2[2], b2[3]);
            }
        }
        // ---- drain once per chunk: IEEE fp32 adds ----
#pragma unroll
        for (int nt = 0; nt < 8; nt++)
#pragma unroll
            for (int i = 0; i < 4; i++) run[nt][i] += cc[nt][i];

        // signal: this thread done reading slot sl
        asm volatile("mbarrier.arrive.shared.b64 _, [%0];" :: "r"(mbE + 8 * sl) : "memory");
    }

    __syncthreads();   // all warps done with mainloop buffers before overlay

    // ---- scatter logits to smem [128][65] (overlays mainloop buffers) ----
    float* lg = (float*)sm;
#pragma unroll
    for (int nt = 0; nt < 8; nt++)
#pragma unroll
        for (int i = 0; i < 4; i++) {
            int tk = R0 + ((i >= 2) ? 8 : 0);
            int ex = nt * 8 + cq * 2 + (i & 1);
            lg[tk * 65 + ex] = run[nt][i];
        }
    __syncthreads();

    if (tid < MT) {
        float sc[NE];
#pragma unroll
        for (int e = 0; e < NE; e++) sc[e] = lg[tid * 65 + e] * WSCALE_INV;  // undo w*32

        float mx = -CUDART_INF_F;
#pragma unroll
        for (int e = 0; e < NE; e++) mx = fmaxf(mx, sc[e]);
        float sum = 0.0f;
#pragma unroll
        for (int e = 0; e < NE; e++) { sc[e] = __expf(sc[e] - mx); sum += sc[e]; }
        float inv = 1.0f / sum;
#pragma unroll
        for (int e = 0; e < NE; e++) sc[e] *= inv;

        const float* bs = (const float*)(sm + OFFB);
        unsigned long long taken = 0ull;
        const int t = t0 + tid;
        float* wout = out + (size_t)t * TOPK;
        float* iout = out + (size_t)TOKENS * TOPK + (size_t)t * TOPK;

#pragma unroll
        for (int sidx = 0; sidx < TOPK; sidx++) {
            float best = -CUDART_INF_F;
            float bsc = 0.0f;
            int be = 0;
#pragma unroll
            for (int e = 0; e < NE; e++) {
                float v = sc[e] + bs[e];
                bool ok = ((taken >> e) & 1ull) == 0ull;
                if (ok && v > best) { best = v; bsc = sc[e]; be = e; }
            }
            taken |= (1ull << be);
            wout[sidx] = bsc;        // ROUTE_SCALE == 1.0
            iout[sidx] = (float)be;
        }
    }
}

extern "C" void kernel_launch(void* const* d_in, const int* in_sizes, int n_in,
                              void* d_out, int out_size) {
    const float* x    = (const float*)d_in[0];
    const float* w    = (const float*)d_in[1];
    const float* bias = (const float*)d_in[2];
    float* out        = (float*)d_out;

    cudaFuncSetAttribute(gate_hmma_kernel,
                         cudaFuncAttributeMaxDynamicSharedMemorySize, SMEMSZ);

    split_w_kernel<<<(NE * DIM) / 256, 256>>>(w);
    gate_hmma_kernel<<<TOKENS / MT, NTH, SMEMSZ>>>(x, bias, out);
}